// round 3
// baseline (speedup 1.0000x reference)
#include <cuda_runtime.h>

// Loss: per joint (3 floats): d = p - l; s2 = d2^2;
// term = (p2 > 0.5) ? (d0^2+d1^2+d2^2)/3 : s2 ; answer = sum(term)/B.
// Layout: [B, 54] fp32 -> B*18 joints of 3 floats; 4 joints = 3 float4 per
// thread-iteration. Single fused kernel: per-block partials in __device__
// scratch, last block (atomic counter) reduces + writes d_out + resets
// counter (deterministic across graph replays, no init kernel).

#define MAX_BLOCKS 4096

__device__ float g_partials[MAX_BLOCKS];
__device__ unsigned int g_count;   // zero-initialized at module load; reset each run

__device__ __forceinline__ float joint_term(float p0, float p1, float p2,
                                            float l0, float l1, float l2) {
    float d0 = p0 - l0, d1 = p1 - l1, d2 = p2 - l2;
    float s2 = d2 * d2;
    float full = (d0 * d0 + d1 * d1 + s2) * (1.0f / 3.0f);
    return (p2 > 0.5f) ? full : s2;
}

__device__ __forceinline__ float block_reduce(float acc, float* ws) {
    #pragma unroll
    for (int off = 16; off; off >>= 1)
        acc += __shfl_down_sync(0xFFFFFFFFu, acc, off);
    int lane = threadIdx.x & 31;
    int wid  = threadIdx.x >> 5;
    if (lane == 0) ws[wid] = acc;
    __syncthreads();
    if (wid == 0) {
        acc = (lane < 8) ? ws[lane] : 0.0f;
        #pragma unroll
        for (int off = 4; off; off >>= 1)
            acc += __shfl_down_sync(0xFFFFFFFFu, acc, off);
    }
    return acc;   // valid in thread 0
}

__global__ void __launch_bounds__(256)
loss_kernel(const float4* __restrict__ P, const float4* __restrict__ L,
            float* __restrict__ out, int ngroups, float inv_b) {
    __shared__ float ws[8];
    __shared__ unsigned int s_last;

    float acc = 0.0f;
    int stride = gridDim.x * blockDim.x;
    for (int g = blockIdx.x * blockDim.x + threadIdx.x; g < ngroups; g += stride) {
        int base = 3 * g;
        float4 pa = P[base + 0];
        float4 pb = P[base + 1];
        float4 pc = P[base + 2];
        float4 la = L[base + 0];
        float4 lb = L[base + 1];
        float4 lc = L[base + 2];
        acc += joint_term(pa.x, pa.y, pa.z, la.x, la.y, la.z);
        acc += joint_term(pa.w, pb.x, pb.y, la.w, lb.x, lb.y);
        acc += joint_term(pb.z, pb.w, pc.x, lb.z, lb.w, lc.x);
        acc += joint_term(pc.y, pc.z, pc.w, lc.y, lc.z, lc.w);
    }

    acc = block_reduce(acc, ws);

    if (threadIdx.x == 0) {
        g_partials[blockIdx.x] = acc;
        __threadfence();
        unsigned int prev = atomicAdd(&g_count, 1u);
        s_last = (prev == gridDim.x - 1) ? 1u : 0u;
    }
    __syncthreads();

    if (s_last) {
        __threadfence();
        float sum = 0.0f;
        for (int i = threadIdx.x; i < gridDim.x; i += blockDim.x)
            sum += g_partials[i];
        sum = block_reduce(sum, ws);
        if (threadIdx.x == 0) {
            out[0] = sum * inv_b;
            g_count = 0;   // reset for next (deterministic) replay
        }
    }
}

extern "C" void kernel_launch(void* const* d_in, const int* in_sizes, int n_in,
                              void* d_out, int out_size) {
    const float4* P = (const float4*)d_in[0];
    const float4* L = (const float4*)d_in[1];
    float* out = (float*)d_out;

    long long total_floats = (long long)in_sizes[0];   // B * 54
    long long B = total_floats / 54;
    int ngroups = (int)(total_floats / 12);            // 4-joint groups

    const int threads = 256;
    const int blocks = 148 * 16;                       // 2368 <= MAX_BLOCKS
    loss_kernel<<<blocks, threads>>>(P, L, out, ngroups, 1.0f / (float)B);
}

// round 4
// speedup vs baseline: 1.0058x; 1.0058x over previous
#include <cuda_runtime.h>

// Loss: per joint (3 floats): d = p - l; s2 = d2^2;
// term = (p2 > 0.5) ? (d0^2+d1^2+d2^2)/3 : s2 ; answer = sum(term)/B.
// Layout: [B, 54] fp32 -> B*18 joints of 3 floats; 4 joints = 3 float4 per
// thread-iteration. Single-wave grid (148 SMs x 8 CTAs of 256 thr = 2048
// resident threads/SM), per-block atomicAdd into d_out, d_out zeroed by a
// memset graph node.

__device__ __forceinline__ float joint_term(float p0, float p1, float p2,
                                            float l0, float l1, float l2) {
    float d0 = p0 - l0, d1 = p1 - l1, d2 = p2 - l2;
    float s2 = d2 * d2;
    float full = (d0 * d0 + d1 * d1 + s2) * (1.0f / 3.0f);
    return (p2 > 0.5f) ? full : s2;
}

__global__ void __launch_bounds__(256)
loss_kernel(const float4* __restrict__ P, const float4* __restrict__ L,
            float* __restrict__ out, int ngroups, float inv_b) {
    float acc = 0.0f;
    int stride = gridDim.x * blockDim.x;
    for (int g = blockIdx.x * blockDim.x + threadIdx.x; g < ngroups; g += stride) {
        int base = 3 * g;
        float4 pa = P[base + 0];
        float4 pb = P[base + 1];
        float4 pc = P[base + 2];
        float4 la = L[base + 0];
        float4 lb = L[base + 1];
        float4 lc = L[base + 2];
        acc += joint_term(pa.x, pa.y, pa.z, la.x, la.y, la.z);
        acc += joint_term(pa.w, pb.x, pb.y, la.w, lb.x, lb.y);
        acc += joint_term(pb.z, pb.w, pc.x, lb.z, lb.w, lc.x);
        acc += joint_term(pc.y, pc.z, pc.w, lc.y, lc.z, lc.w);
    }

    // warp reduce
    #pragma unroll
    for (int off = 16; off; off >>= 1)
        acc += __shfl_down_sync(0xFFFFFFFFu, acc, off);

    __shared__ float ws[8];
    int lane = threadIdx.x & 31;
    int wid  = threadIdx.x >> 5;
    if (lane == 0) ws[wid] = acc;
    __syncthreads();
    if (wid == 0) {
        acc = (lane < 8) ? ws[lane] : 0.0f;
        #pragma unroll
        for (int off = 4; off; off >>= 1)
            acc += __shfl_down_sync(0xFFFFFFFFu, acc, off);
        if (lane == 0) atomicAdd(out, acc * inv_b);
    }
}

extern "C" void kernel_launch(void* const* d_in, const int* in_sizes, int n_in,
                              void* d_out, int out_size) {
    const float4* P = (const float4*)d_in[0];
    const float4* L = (const float4*)d_in[1];
    float* out = (float*)d_out;

    long long total_floats = (long long)in_sizes[0];   // B * 54
    long long B = total_floats / 54;
    int ngroups = (int)(total_floats / 12);            // 4-joint groups

    cudaMemsetAsync(out, 0, sizeof(float));

    const int threads = 256;
    const int blocks = 148 * 8;                        // exactly one wave
    loss_kernel<<<blocks, threads>>>(P, L, out, ngroups, 1.0f / (float)B);
}